// round 11
// baseline (speedup 1.0000x reference)
#include <cuda_runtime.h>
#include <cuda_fp16.h>
#include <cstdint>

// LSTMPredictor B=256,T=1024,HID=150 — R10: R9 HMMA core + tail surgery.
// 128 CTAs x 256 threads (8 warps), 2 batches/CTA, mma.sync m16n8k16
// (fp16 in, fp32 acc). Warp w owns M-tiles {w+8i}: 4 tiles' A-fragments in
// registers, 5th in lane-linear smem. Changes vs R9:
//  - all activations via tanh.approx.f32 (1 MUFU); sigmoid = 0.5*tanh(x/2)+0.5
//  - x*W_ih + bias folded into the (parallel) D-extraction lanes, so the
//    barrier-serialized pointwise phase is just activations + c/h update
//  - update threads shed their pinned wih/bias registers (scheduling slack)

namespace {

constexpr int HID = 150, TT = 1024, NCTA = 128, NTHR = 256;
constexpr int KT = 10;            // K-tiles of 16 (K padded to 160)
constexpr int HKP = 168;          // h pitch in halves (84 words: bank-clean)

// dynamic smem offsets (bytes)
constexpr int OFF_HK   = 0;                 // fp16 h [8][168] = 2688
constexpr int OFF_HBUF = 2688;              // fp32 h [2][152] = 1216
constexpr int OFF_G2   = 3904;              // float2 gates [640] = 5120
constexpr int OFF_WLIN = 9024;              // fp32 [160] = 640
constexpr int OFF_BIAS = 9664;              // fp32 [640] = 2560 (zero-padded)
constexpr int OFF_WIH  = 12224;             // fp32 [640] = 2560 (zero-padded)
constexpr int OFF_W5   = 14784;             // uint4 A-frags tile i=4: 40960
constexpr int OFF_XIN  = 55744;             // fp32 [2][1024] = 8192
constexpr int SMEM_BYTES = 63936;

__device__ __forceinline__ float tanhapx(float x) {
    float y;
    asm("tanh.approx.f32 %0, %1;" : "=f"(y) : "f"(x));
    return y;
}
__device__ __forceinline__ float sigapx(float x) {
    return fmaf(tanhapx(0.5f * x), 0.5f, 0.5f);
}

__device__ __forceinline__ void mma16816(float& d0, float& d1, float& d2,
                                         float& d3, uint32_t a0, uint32_t a1,
                                         uint32_t a2, uint32_t a3,
                                         uint32_t b0, uint32_t b1) {
    asm volatile(
        "mma.sync.aligned.m16n8k16.row.col.f32.f16.f16.f32 "
        "{%0,%1,%2,%3}, {%4,%5,%6,%7}, {%8,%9}, {%0,%1,%2,%3};"
        : "+f"(d0), "+f"(d1), "+f"(d2), "+f"(d3)
        : "r"(a0), "r"(a1), "r"(a2), "r"(a3), "r"(b0), "r"(b1));
}

__device__ __forceinline__ float wel(const float* W, int r, int c) {
    return (r < 600 && c < HID) ? W[r * HID + c] : 0.f;
}
__device__ __forceinline__ uint32_t h2u(__half2 v) {
    return *reinterpret_cast<uint32_t*>(&v);
}

} // namespace

__global__ void __launch_bounds__(NTHR, 1)
lstm_hmma_kernel(const float* __restrict__ input,   // [256][1024]
                 const float* __restrict__ W_ih,    // [600][1]
                 const float* __restrict__ W_hh,    // [600][150]
                 const float* __restrict__ b_ih,    // [600]
                 const float* __restrict__ b_hh,    // [600]
                 const float* __restrict__ W_lin,   // [1][150]
                 const float* __restrict__ b_lin,   // [1]
                 float* __restrict__ out)           // [256][1024]
{
    extern __shared__ char smem[];
    __half* hk     = reinterpret_cast<__half*>(smem + OFF_HK);
    float*  hbuf   = reinterpret_cast<float*>(smem + OFF_HBUF);
    float2* g2     = reinterpret_cast<float2*>(smem + OFF_G2);
    float*  wlin_s = reinterpret_cast<float*>(smem + OFF_WLIN);
    float*  bias_s = reinterpret_cast<float*>(smem + OFF_BIAS);
    float*  wih_s  = reinterpret_cast<float*>(smem + OFF_WIH);
    uint4*  w5     = reinterpret_cast<uint4*>(smem + OFF_W5);
    float*  xin    = reinterpret_cast<float*>(smem + OFF_XIN);

    const int tid  = threadIdx.x;
    const int wid  = tid >> 5;
    const int lane = tid & 31;
    const int g    = lane >> 2;
    const int tig  = lane & 3;
    const int b0   = blockIdx.x * 2;

    // ---- one-time init ----
    for (int i = tid; i < 8 * HKP; i += NTHR) hk[i] = __half(0);
    for (int i = tid; i < 2 * 152; i += NTHR) hbuf[i] = 0.f;
    for (int i = tid; i < HID; i += NTHR) wlin_s[i] = W_lin[i];
    for (int i = tid; i < 640; i += NTHR) {       // zero-padded rows >= 600
        bias_s[i] = (i < 600) ? (b_ih[i] + b_hh[i]) : 0.f;
        wih_s[i]  = (i < 600) ? W_ih[i] : 0.f;
    }
    for (int i = tid; i < 2 * TT; i += NTHR)
        xin[i] = input[(b0 + (i >> 10)) * TT + (i & (TT - 1))];

    // A fragments (m16n8k16 .row): mtile = wid + 8*i; i<4 regs, i=4 smem.
    uint32_t af[4][KT][4];
#pragma unroll
    for (int i = 0; i < 5; ++i) {
        const int mb = 16 * (wid + 8 * i);
#pragma unroll
        for (int kt = 0; kt < KT; ++kt) {
            const int kb = 16 * kt + 2 * tig;
            const int r0 = mb + g, r1 = mb + g + 8;
            uint32_t f0 = h2u(__floats2half2_rn(wel(W_hh, r0, kb),
                                                wel(W_hh, r0, kb + 1)));
            uint32_t f1 = h2u(__floats2half2_rn(wel(W_hh, r1, kb),
                                                wel(W_hh, r1, kb + 1)));
            uint32_t f2 = h2u(__floats2half2_rn(wel(W_hh, r0, kb + 8),
                                                wel(W_hh, r0, kb + 9)));
            uint32_t f3 = h2u(__floats2half2_rn(wel(W_hh, r1, kb + 8),
                                                wel(W_hh, r1, kb + 9)));
            if (i < 4) {
                af[i][kt][0] = f0; af[i][kt][1] = f1;
                af[i][kt][2] = f2; af[i][kt][3] = f3;
            } else {
                w5[(wid * KT + kt) * 32 + lane] = make_uint4(f0, f1, f2, f3);
            }
        }
    }

    float c0 = 0.f, c1 = 0.f;
    const float blin = b_lin[0];

    __syncthreads();

    for (int t = 0; t < TT; ++t) {
        // ---- overlapped output: out[t-1] from hbuf = h_{t-1} (warps 4,5) ----
        if (t && (wid == 4 || wid == 5)) {
            const int bb = wid - 4;
            float s = 0.f;
#pragma unroll
            for (int m = 0; m < 5; ++m) {
                const int jj = lane + 32 * m;
                if (jj < HID) s = fmaf(hbuf[bb * 152 + jj], wlin_s[jj], s);
            }
#pragma unroll
            for (int off = 16; off; off >>= 1)
                s += __shfl_down_sync(0xffffffffu, s, off);
            if (lane == 0) out[(b0 + bb) * TT + (t - 1)] = s + blin;
        }

        // ---- B fragments from h_{t-1} (conflict-free LDS.32) ----
        uint32_t bf[KT][2];
#pragma unroll
        for (int kt = 0; kt < KT; ++kt) {
            const int base = g * HKP + 16 * kt + 2 * tig;
            bf[kt][0] = *reinterpret_cast<const uint32_t*>(hk + base);
            bf[kt][1] = *reinterpret_cast<const uint32_t*>(hk + base + 8);
        }

        const float x0 = xin[t], x1 = xin[TT + t];

        // ---- 5 M-tiles x 10 K-tiles of HMMA; extraction folds x*wih+bias --
#pragma unroll
        for (int i = 0; i < 5; ++i) {
            float d0 = 0.f, d1 = 0.f, d2 = 0.f, d3 = 0.f;
            if (i < 4) {
#pragma unroll
                for (int kt = 0; kt < KT; ++kt)
                    mma16816(d0, d1, d2, d3, af[i][kt][0], af[i][kt][1],
                             af[i][kt][2], af[i][kt][3], bf[kt][0], bf[kt][1]);
            } else {
#pragma unroll
                for (int kt = 0; kt < KT; ++kt) {
                    const uint4 q = w5[(wid * KT + kt) * 32 + lane];
                    mma16816(d0, d1, d2, d3, q.x, q.y, q.z, q.w,
                             bf[kt][0], bf[kt][1]);
                }
            }
            if (tig == 0) {           // cols 0,1 live here; fold input+bias
                const int mb = 16 * (wid + 8 * i);
                const int r0 = mb + g, r1 = mb + 8 + g;
                const float w0 = wih_s[r0], bi0 = bias_s[r0];
                const float w1 = wih_s[r1], bi1 = bias_s[r1];
                g2[r0] = make_float2(d0 + fmaf(x0, w0, bi0),
                                     d1 + fmaf(x1, w0, bi0));
                g2[r1] = make_float2(d2 + fmaf(x0, w1, bi1),
                                     d3 + fmaf(x1, w1, bi1));
            }
        }
        __syncthreads();              // gates ready; hk reads complete

        // ---- pointwise LSTM update: thread j < 150 (short tail now) ----
        if (tid < HID) {
            const int j = tid;
            const float2 gi = g2[j],         gf = g2[HID + j];
            const float2 gg = g2[2*HID + j], go = g2[3*HID + j];
            c0 = fmaf(sigapx(gf.x), c0, sigapx(gi.x) * tanhapx(gg.x));
            c1 = fmaf(sigapx(gf.y), c1, sigapx(gi.y) * tanhapx(gg.y));
            const float h0 = sigapx(go.x) * tanhapx(c0);
            const float h1 = sigapx(go.y) * tanhapx(c1);
            hbuf[j]       = h0;
            hbuf[152 + j] = h1;
            hk[j]         = __float2half(h0);
            hk[HKP + j]   = __float2half(h1);
        }
        __syncthreads();              // h_t visible for next step
    }

    // ---- epilogue: out[TT-1] ----
    if (wid == 4 || wid == 5) {
        const int bb = wid - 4;
        float s = 0.f;
#pragma unroll
        for (int m = 0; m < 5; ++m) {
            const int jj = lane + 32 * m;
            if (jj < HID) s = fmaf(hbuf[bb * 152 + jj], wlin_s[jj], s);
        }
#pragma unroll
        for (int off = 16; off; off >>= 1)
            s += __shfl_down_sync(0xffffffffu, s, off);
        if (lane == 0) out[(b0 + bb) * TT + (TT - 1)] = s + blin;
    }
}

extern "C" void kernel_launch(void* const* d_in, const int* in_sizes, int n_in,
                              void* d_out, int out_size) {
    const float* input = (const float*)d_in[0];
    const float* W_ih  = (const float*)d_in[1];
    const float* W_hh  = (const float*)d_in[2];
    const float* b_ih  = (const float*)d_in[3];
    const float* b_hh  = (const float*)d_in[4];
    const float* W_lin = (const float*)d_in[5];
    const float* b_lin = (const float*)d_in[6];
    float* out = (float*)d_out;

    cudaFuncSetAttribute(lstm_hmma_kernel,
                         cudaFuncAttributeMaxDynamicSharedMemorySize, SMEM_BYTES);
    lstm_hmma_kernel<<<NCTA, NTHR, SMEM_BYTES>>>(input, W_ih, W_hh, b_ih, b_hh,
                                                 W_lin, b_lin, out);
}

// round 12
// speedup vs baseline: 1.4226x; 1.4226x over previous
#include <cuda_runtime.h>
#include <cuda_fp16.h>
#include <cstdint>

// LSTMPredictor B=256,T=1024,HID=150 — R12: exact R9 HMMA structure
// (975us known-good register allocation) with ONE change: pointwise
// activations via tanh.approx.f32 (MUFU.TANH), sigmoid = 0.5*tanh(x/2)+0.5.
// R10's extraction-fold is reverted — it pushed live ranges into the MMA
// loop, spilled at 254 regs (HBM 1->1154 GB/s), and cost 26%.
// 128 CTAs x 256 threads (8 warps), 2 batches/CTA, mma.sync m16n8k16
// fp16->fp32. Warp w owns M-tiles {w+8i}: tiles i<4 A-fragments pinned in
// registers, tile i=4 in lane-linear smem (conflict-free LDS.128).

namespace {

constexpr int HID = 150, TT = 1024, NCTA = 128, NTHR = 256;
constexpr int KT = 10;            // K-tiles of 16 (K padded to 160)
constexpr int HKP = 168;          // h pitch in halves (84 words: bank-clean)

// dynamic smem offsets (bytes)
constexpr int OFF_HK   = 0;                 // fp16 h [8][168] = 2688
constexpr int OFF_HBUF = 2688;              // fp32 h [2][152] = 1216
constexpr int OFF_G2   = 3904;              // float2 gates [640] = 5120
constexpr int OFF_WLIN = 9024;              // fp32 [160] = 640
constexpr int OFF_W5   = 9664;              // uint4 A-frags tile i=4: 40960
constexpr int OFF_XIN  = 50624;             // fp32 [2][1024] = 8192
constexpr int SMEM_BYTES = 58816;

__device__ __forceinline__ float tanhapx(float x) {
    float y;
    asm("tanh.approx.f32 %0, %1;" : "=f"(y) : "f"(x));
    return y;
}
__device__ __forceinline__ float sigapx(float x) {
    return fmaf(tanhapx(0.5f * x), 0.5f, 0.5f);
}

__device__ __forceinline__ void mma16816(float& d0, float& d1, float& d2,
                                         float& d3, uint32_t a0, uint32_t a1,
                                         uint32_t a2, uint32_t a3,
                                         uint32_t b0, uint32_t b1) {
    asm volatile(
        "mma.sync.aligned.m16n8k16.row.col.f32.f16.f16.f32 "
        "{%0,%1,%2,%3}, {%4,%5,%6,%7}, {%8,%9}, {%0,%1,%2,%3};"
        : "+f"(d0), "+f"(d1), "+f"(d2), "+f"(d3)
        : "r"(a0), "r"(a1), "r"(a2), "r"(a3), "r"(b0), "r"(b1));
}

__device__ __forceinline__ float wel(const float* W, int r, int c) {
    return (r < 600 && c < HID) ? W[r * HID + c] : 0.f;
}
__device__ __forceinline__ uint32_t h2u(__half2 v) {
    return *reinterpret_cast<uint32_t*>(&v);
}

} // namespace

__global__ void __launch_bounds__(NTHR, 1)
lstm_hmma_kernel(const float* __restrict__ input,   // [256][1024]
                 const float* __restrict__ W_ih,    // [600][1]
                 const float* __restrict__ W_hh,    // [600][150]
                 const float* __restrict__ b_ih,    // [600]
                 const float* __restrict__ b_hh,    // [600]
                 const float* __restrict__ W_lin,   // [1][150]
                 const float* __restrict__ b_lin,   // [1]
                 float* __restrict__ out)           // [256][1024]
{
    extern __shared__ char smem[];
    __half* hk     = reinterpret_cast<__half*>(smem + OFF_HK);
    float*  hbuf   = reinterpret_cast<float*>(smem + OFF_HBUF);
    float2* g2     = reinterpret_cast<float2*>(smem + OFF_G2);
    float*  wlin_s = reinterpret_cast<float*>(smem + OFF_WLIN);
    uint4*  w5     = reinterpret_cast<uint4*>(smem + OFF_W5);
    float*  xin    = reinterpret_cast<float*>(smem + OFF_XIN);

    const int tid  = threadIdx.x;
    const int wid  = tid >> 5;
    const int lane = tid & 31;
    const int g    = lane >> 2;      // fragment row-group 0..7
    const int tig  = lane & 3;       // thread-in-group
    const int b0   = blockIdx.x * 2;

    // ---- one-time init ----
    for (int i = tid; i < 8 * HKP; i += NTHR) hk[i] = __half(0);
    for (int i = tid; i < 2 * 152; i += NTHR) hbuf[i] = 0.f;
    for (int i = tid; i < HID; i += NTHR) wlin_s[i] = W_lin[i];
    for (int i = tid; i < 2 * TT; i += NTHR)
        xin[i] = input[(b0 + (i >> 10)) * TT + (i & (TT - 1))];

    // A fragments: m16n8k16 .row layout. mtile = wid + 8*i.
    uint32_t af[4][KT][4];
#pragma unroll
    for (int i = 0; i < 5; ++i) {
        const int mb = 16 * (wid + 8 * i);
#pragma unroll
        for (int kt = 0; kt < KT; ++kt) {
            const int kb = 16 * kt + 2 * tig;
            const int r0 = mb + g, r1 = mb + g + 8;
            uint32_t f0 = h2u(__floats2half2_rn(wel(W_hh, r0, kb),
                                                wel(W_hh, r0, kb + 1)));
            uint32_t f1 = h2u(__floats2half2_rn(wel(W_hh, r1, kb),
                                                wel(W_hh, r1, kb + 1)));
            uint32_t f2 = h2u(__floats2half2_rn(wel(W_hh, r0, kb + 8),
                                                wel(W_hh, r0, kb + 9)));
            uint32_t f3 = h2u(__floats2half2_rn(wel(W_hh, r1, kb + 8),
                                                wel(W_hh, r1, kb + 9)));
            if (i < 4) {
                af[i][kt][0] = f0; af[i][kt][1] = f1;
                af[i][kt][2] = f2; af[i][kt][3] = f3;
            } else {
                w5[(wid * KT + kt) * 32 + lane] = make_uint4(f0, f1, f2, f3);
            }
        }
    }

    // Update-thread constants (gate rows j, 150+j, 300+j, 450+j)
    float wih[4], bia[4];
    if (tid < HID) {
#pragma unroll
        for (int r = 0; r < 4; ++r) {
            const int row = r * HID + tid;
            wih[r] = W_ih[row];
            bia[r] = b_ih[row] + b_hh[row];
        }
    }
    float c0 = 0.f, c1 = 0.f;
    const float blin = b_lin[0];

    __syncthreads();

    for (int t = 0; t < TT; ++t) {
        // ---- overlapped output: out[t-1] from hbuf = h_{t-1} (warps 4,5) ----
        if (t && (wid == 4 || wid == 5)) {
            const int bb = wid - 4;
            float s = 0.f;
#pragma unroll
            for (int m = 0; m < 5; ++m) {
                const int jj = lane + 32 * m;
                if (jj < HID) s = fmaf(hbuf[bb * 152 + jj], wlin_s[jj], s);
            }
#pragma unroll
            for (int off = 16; off; off >>= 1)
                s += __shfl_down_sync(0xffffffffu, s, off);
            if (lane == 0) out[(b0 + bb) * TT + (t - 1)] = s + blin;
        }

        // ---- B fragments from h_{t-1} (conflict-free LDS.32) ----
        uint32_t bf[KT][2];
#pragma unroll
        for (int kt = 0; kt < KT; ++kt) {
            const int base = g * HKP + 16 * kt + 2 * tig;
            bf[kt][0] = *reinterpret_cast<const uint32_t*>(hk + base);
            bf[kt][1] = *reinterpret_cast<const uint32_t*>(hk + base + 8);
        }

        // ---- 5 M-tiles x 10 K-tiles of HMMA ----
#pragma unroll
        for (int i = 0; i < 5; ++i) {
            float d0 = 0.f, d1 = 0.f, d2 = 0.f, d3 = 0.f;
            if (i < 4) {
#pragma unroll
                for (int kt = 0; kt < KT; ++kt)
                    mma16816(d0, d1, d2, d3, af[i][kt][0], af[i][kt][1],
                             af[i][kt][2], af[i][kt][3], bf[kt][0], bf[kt][1]);
            } else {
#pragma unroll
                for (int kt = 0; kt < KT; ++kt) {
                    const uint4 q = w5[(wid * KT + kt) * 32 + lane];
                    mma16816(d0, d1, d2, d3, q.x, q.y, q.z, q.w,
                             bf[kt][0], bf[kt][1]);
                }
            }
            if (tig == 0) {           // cols 0,1 live in these lanes
                const int mb = 16 * (wid + 8 * i);
                g2[mb + g]     = make_float2(d0, d1);
                g2[mb + 8 + g] = make_float2(d2, d3);
            }
        }
        __syncthreads();              // gates ready; hk reads complete

        // ---- pointwise LSTM update: thread j < 150 ----
        if (tid < HID) {
            const int j = tid;
            const float x0 = xin[t], x1 = xin[TT + t];
            float2 gi = g2[j],         gf = g2[HID + j];
            float2 gg = g2[2*HID + j], go = g2[3*HID + j];
            gi.x += fmaf(x0, wih[0], bia[0]); gi.y += fmaf(x1, wih[0], bia[0]);
            gf.x += fmaf(x0, wih[1], bia[1]); gf.y += fmaf(x1, wih[1], bia[1]);
            gg.x += fmaf(x0, wih[2], bia[2]); gg.y += fmaf(x1, wih[2], bia[2]);
            go.x += fmaf(x0, wih[3], bia[3]); go.y += fmaf(x1, wih[3], bia[3]);
            c0 = fmaf(sigapx(gf.x), c0, sigapx(gi.x) * tanhapx(gg.x));
            c1 = fmaf(sigapx(gf.y), c1, sigapx(gi.y) * tanhapx(gg.y));
            const float h0 = sigapx(go.x) * tanhapx(c0);
            const float h1 = sigapx(go.y) * tanhapx(c1);
            hbuf[j]       = h0;
            hbuf[152 + j] = h1;
            hk[j]         = __float2half(h0);   // B rows n=0,1; n>=2 stay 0
            hk[HKP + j]   = __float2half(h1);
        }
        __syncthreads();              // h_t visible for next step
    }

    // ---- epilogue: out[TT-1] ----
    if (wid == 4 || wid == 5) {
        const int bb = wid - 4;
        float s = 0.f;
#pragma unroll
        for (int m = 0; m < 5; ++m) {
            const int jj = lane + 32 * m;
            if (jj < HID) s = fmaf(hbuf[bb * 152 + jj], wlin_s[jj], s);
        }
#pragma unroll
        for (int off = 16; off; off >>= 1)
            s += __shfl_down_sync(0xffffffffu, s, off);
        if (lane == 0) out[(b0 + bb) * TT + (TT - 1)] = s + blin;
    }
}

extern "C" void kernel_launch(void* const* d_in, const int* in_sizes, int n_in,
                              void* d_out, int out_size) {
    const float* input = (const float*)d_in[0];
    const float* W_ih  = (const float*)d_in[1];
    const float* W_hh  = (const float*)d_in[2];
    const float* b_ih  = (const float*)d_in[3];
    const float* b_hh  = (const float*)d_in[4];
    const float* W_lin = (const float*)d_in[5];
    const float* b_lin = (const float*)d_in[6];
    float* out = (float*)d_out;

    cudaFuncSetAttribute(lstm_hmma_kernel,
                         cudaFuncAttributeMaxDynamicSharedMemorySize, SMEM_BYTES);
    lstm_hmma_kernel<<<NCTA, NTHR, SMEM_BYTES>>>(input, W_ih, W_hh, b_ih, b_hh,
                                                 W_lin, b_lin, out);
}